// round 8
// baseline (speedup 1.0000x reference)
#include <cuda_runtime.h>
#include <cstdint>

#define NPTS 8192
#define D 200
#define ROW_BYTES 256              // int8 rows zero-padded to 256 k
#define NCHUNK 14                  // 14 x 16B = 224 bytes loaded (K=224)
#define NKS 7                      // 7 k-steps of 32
#define TM 128
#define NT (NPTS / TM)             // 64
#define NTRI (NT * (NT + 1) / 2)   // 2080
#define TPB 256
#define TILE_BYTES (TM * ROW_BYTES)      // 32 KB
#define SMEM_DYN (2 * TILE_BYTES)        // A + B
#define QSCALE (127.0f / 5.0f)
#define DSCALE (5.0f / 127.0f)

// ---------------- device scratch (no allocations allowed) ----------------
__device__ __align__(16) unsigned char g_xq[(size_t)NPTS * ROW_BYTES]; // 2 MB int8
__device__ int g_isq[NPTS];
__device__ float g_part[NTRI];
__device__ int g_is64;
__device__ unsigned int g_cnt;

#define CP16(d, s) \
    asm volatile("cp.async.cg.shared.global [%0], [%1], 16;" :: "r"(d), "l"(s) : "memory")
#define CPC()  asm volatile("cp.async.commit_group;" ::: "memory")
#define CPW0() asm volatile("cp.async.wait_group 0;" ::: "memory")

// ---------------------------------------------------------------------------
// Kernel 1: quantize x -> int8 (scale 127/5, zero-padded), exact int sq.
// Block 0 additionally: label-dtype detection + counter reset.
// One warp per row; lanes 0..24 hold 8 valid k each.
// ---------------------------------------------------------------------------
__global__ void prep_kernel(const float* __restrict__ x,
                            const int* __restrict__ lab32) {
    int row  = blockIdx.x * (TPB / 32) + (threadIdx.x >> 5);
    int lane = threadIdx.x & 31;
    int k0   = lane * 8;
    int isq  = 0;
    uint32_t w0 = 0, w1 = 0;
    if (k0 < D) {
        const float4* xr = (const float4*)(x + (size_t)row * D);
        float4 f0 = xr[lane * 2];
        float4 f1 = xr[lane * 2 + 1];
        int q[8];
        q[0] = __float2int_rn(f0.x * QSCALE); q[1] = __float2int_rn(f0.y * QSCALE);
        q[2] = __float2int_rn(f0.z * QSCALE); q[3] = __float2int_rn(f0.w * QSCALE);
        q[4] = __float2int_rn(f1.x * QSCALE); q[5] = __float2int_rn(f1.y * QSCALE);
        q[6] = __float2int_rn(f1.z * QSCALE); q[7] = __float2int_rn(f1.w * QSCALE);
#pragma unroll
        for (int i = 0; i < 8; i++) q[i] = max(-127, min(127, q[i]));
        w0 = (uint32_t)(q[0] & 255) | ((uint32_t)(q[1] & 255) << 8) |
             ((uint32_t)(q[2] & 255) << 16) | ((uint32_t)(q[3] & 255) << 24);
        w1 = (uint32_t)(q[4] & 255) | ((uint32_t)(q[5] & 255) << 8) |
             ((uint32_t)(q[6] & 255) << 16) | ((uint32_t)(q[7] & 255) << 24);
        isq = __dp4a((int)w0, (int)w0, __dp4a((int)w1, (int)w1, (int)0));
    }
    *(uint2*)(g_xq + (size_t)row * ROW_BYTES + k0) = make_uint2(w0, w1);
#pragma unroll
    for (int o = 16; o; o >>= 1) isq += __shfl_xor_sync(0xffffffffu, isq, o);
    if (lane == 0) g_isq[row] = isq;

    if (blockIdx.x == 0) {  // label dtype detection (global property)
        __shared__ int any;
        if (threadIdx.x == 0) { any = 0; g_cnt = 0; }
        __syncthreads();
        int a = 0;
        for (int i = 2 * threadIdx.x + 1; i < NPTS; i += 2 * TPB) a |= lab32[i];
        if (a) atomicOr(&any, 1);
        __syncthreads();
        if (threadIdx.x == 0) g_is64 = (any == 0) ? 1 : 0;
    }
}

// ---------------------------------------------------------------------------
// Kernel 2: triangular grid of 128x128 tiles, mma.sync s8 m16n8k32.
// d^2 * (127/5)^2 is EXACT int32; dist = (5/127)*sqrt(int).
// ---------------------------------------------------------------------------
__global__ void __launch_bounds__(TPB, 2)
pair_kernel(const int* __restrict__ lab32, float* __restrict__ out) {
    extern __shared__ __align__(128) unsigned char dyn[];
    __shared__ int   sqA[TM], sqB[TM];
    __shared__ int   lA[TM], lB[TM];
    __shared__ float red[TPB / 32];
    __shared__ int    s_last;
    __shared__ double dred[TPB];

    const int t    = threadIdx.x;
    const int wid  = t >> 5;
    const int lane = t & 31;

    int bl = blockIdx.x, ti = 0;
    while (bl >= NT - ti) { bl -= NT - ti; ti++; }
    const int tj = ti + bl;

    const uint32_t dynA = (uint32_t)__cvta_generic_to_shared(dyn);
    const unsigned char* gA = g_xq + (size_t)(ti * TM) * ROW_BYTES;
    const unsigned char* gB = g_xq + (size_t)(tj * TM) * ROW_BYTES;

    // Load both operand tiles (14 chunks x 128 rows x 2 operands).
    {
        int row = t & 127, op = t >> 7;
        const unsigned char* gp = op ? gB : gA;
        uint32_t dst0 = dynA + op * TILE_BYTES + row * ROW_BYTES;
        int rx = row & 7;
#pragma unroll
        for (int c = 0; c < NCHUNK; c++)
            CP16(dst0 + ((c ^ rx) << 4), gp + (size_t)row * ROW_BYTES + c * 16);
        CPC();
    }

    {
        int is64 = g_is64;
        if (t < TM) {
            int g = ti * TM + t;
            sqA[t] = g_isq[g];
            lA[t]  = is64 ? lab32[2 * g] : lab32[g];
        } else {
            int u = t - TM, g = tj * TM + u;
            sqB[u] = g_isq[g];
            lB[u]  = is64 ? lab32[2 * g] : lab32[g];
        }
    }

    const int warp_m = wid >> 1;   // 0..3 -> 32 m-rows
    const int warp_n = wid & 1;    // 0..1 -> 64 n-cols

    // ldmatrix lane address components
    uint32_t abase[2], arx[2];
#pragma unroll
    for (int f = 0; f < 2; f++) {
        uint32_t arow = warp_m * 32 + f * 16 + (lane & 15);
        abase[f] = dynA + arow * ROW_BYTES;
        arx[f]   = arow & 7;
    }
    const uint32_t akc = lane >> 4;          // +0 / +1 chunk
    uint32_t bbase[4], brx[4];
#pragma unroll
    for (int h = 0; h < 4; h++) {
        uint32_t brow = warp_n * 64 + h * 16 + (lane & 7) + ((lane >> 4) << 3);
        bbase[h] = dynA + TILE_BYTES + brow * ROW_BYTES;
        brx[h]   = brow & 7;
    }
    const uint32_t bkc = (lane >> 3) & 1;

    int acc[2][8][4];
#pragma unroll
    for (int f = 0; f < 2; f++)
#pragma unroll
        for (int j = 0; j < 8; j++)
#pragma unroll
            for (int e = 0; e < 4; e++) acc[f][j][e] = 0;

    CPW0();
    __syncthreads();

#pragma unroll
    for (int ks = 0; ks < NKS; ks++) {
        const uint32_t c0 = (uint32_t)ks * 2;
        uint32_t a_[2][4], b_[8][2];
#pragma unroll
        for (int f = 0; f < 2; f++) {
            uint32_t ad = abase[f] + (((c0 + akc) ^ arx[f]) << 4);
            asm volatile("ldmatrix.sync.aligned.m8n8.x4.shared.b16 {%0,%1,%2,%3}, [%4];"
                : "=r"(a_[f][0]), "=r"(a_[f][1]), "=r"(a_[f][2]), "=r"(a_[f][3]) : "r"(ad));
        }
#pragma unroll
        for (int h = 0; h < 4; h++) {
            uint32_t bd = bbase[h] + (((c0 + bkc) ^ brx[h]) << 4);
            asm volatile("ldmatrix.sync.aligned.m8n8.x4.shared.b16 {%0,%1,%2,%3}, [%4];"
                : "=r"(b_[2 * h][0]), "=r"(b_[2 * h][1]),
                  "=r"(b_[2 * h + 1][0]), "=r"(b_[2 * h + 1][1]) : "r"(bd));
        }
#pragma unroll
        for (int f = 0; f < 2; f++)
#pragma unroll
            for (int j = 0; j < 8; j++)
                asm volatile(
                    "mma.sync.aligned.m16n8k32.row.col.s32.s8.s8.s32 "
                    "{%0,%1,%2,%3}, {%4,%5,%6,%7}, {%8,%9}, {%0,%1,%2,%3};"
                    : "+r"(acc[f][j][0]), "+r"(acc[f][j][1]),
                      "+r"(acc[f][j][2]), "+r"(acc[f][j][3])
                    : "r"(a_[f][0]), "r"(a_[f][1]), "r"(a_[f][2]), "r"(a_[f][3]),
                      "r"(b_[j][0]), "r"(b_[j][1]));
    }

    // Epilogue: exact integer d2, dist = sqrt, sign, strict upper predicate.
    float lsum = 0.f;
    const int qrow = lane >> 2;
    const int qcol = (lane & 3) * 2;
#pragma unroll
    for (int f = 0; f < 2; f++) {
        int m0 = warp_m * 32 + f * 16 + qrow;
#pragma unroll
        for (int j = 0; j < 8; j++) {
            int n0 = warp_n * 64 + j * 8 + qcol;
#pragma unroll
            for (int e = 0; e < 4; e++) {
                int m_loc = m0 + ((e >> 1) << 3);
                int n_loc = n0 + (e & 1);
                int gm = ti * TM + m_loc;
                int gn = tj * TM + n_loc;
                int d2i = sqA[m_loc] + sqB[n_loc] - 2 * acc[f][j][e];  // exact, >= 0
                float dist = sqrtf((float)d2i);
                float sgn  = (lA[m_loc] == lB[n_loc]) ? dist : -dist;
                if (gn > gm) lsum += sgn;
            }
        }
    }
#pragma unroll
    for (int o = 16; o; o >>= 1) lsum += __shfl_xor_sync(0xffffffffu, lsum, o);
    if (lane == 0) red[wid] = lsum;
    __syncthreads();
    if (t == 0) {
        float s = 0.f;
#pragma unroll
        for (int w = 0; w < TPB / 32; w++) s += red[w];
        g_part[blockIdx.x] = s * DSCALE;
    }

    // ---- last-CTA-done fused final reduction (deterministic order) ----
    __threadfence();
    if (t == 0) {
        unsigned old = atomicAdd(&g_cnt, 1u);
        s_last = (old == NTRI - 1) ? 1 : 0;
    }
    __syncthreads();
    if (s_last) {
        __threadfence();
        double a = 0.0;
        for (int i = t; i < NTRI; i += TPB) a += (double)g_part[i];
        dred[t] = a;
        __syncthreads();
        for (int o = TPB / 2; o; o >>= 1) {
            if (t < o) dred[t] += dred[t + o];
            __syncthreads();
        }
        if (t == 0) out[0] = (float)(2.0 * dred[0] / (double)NPTS);
    }
}

// ---------------------------------------------------------------------------
extern "C" void kernel_launch(void* const* d_in, const int* in_sizes, int n_in,
                              void* d_out, int out_size) {
    const float* x     = (const float*)d_in[0];
    const int*   lab32 = (const int*)d_in[1];
    float*       outp  = (float*)d_out;

    cudaFuncSetAttribute(pair_kernel, cudaFuncAttributeMaxDynamicSharedMemorySize,
                         SMEM_DYN);

    prep_kernel<<<NPTS / (TPB / 32), TPB>>>(x, lab32);
    pair_kernel<<<NTRI, TPB, SMEM_DYN>>>(lab32, outp);
}

// round 9
// speedup vs baseline: 1.6927x; 1.6927x over previous
#include <cuda_runtime.h>
#include <cuda_bf16.h>
#include <cstdint>

#define NPTS 8192
#define D 200
#define ROW_BYTES 512              // bf16 rows zero-padded to 256 k
#define TM 128
#define NT (NPTS / TM)             // 64
#define NTRI (NT * (NT + 1) / 2)   // 2080
#define TPB 256
#define TILE_BYTES (TM * 128)      // 16 KB per operand buffer
#define SMEM_DYN (4 * TILE_BYTES)  // A0 A1 B0 B1

// ---------------- device scratch (no allocations allowed) ----------------
__device__ __align__(16) unsigned char g_xb[(size_t)NPTS * ROW_BYTES]; // 4 MB bf16
__device__ float g_sq[NPTS];
__device__ float g_part[NTRI];
__device__ int   g_is64;
__device__ unsigned int g_cnt;

#define CP16(d, s) \
    asm volatile("cp.async.cg.shared.global [%0], [%1], 16;" :: "r"(d), "l"(s) : "memory")
#define CPC()  asm volatile("cp.async.commit_group;" ::: "memory")
#define CPW1() asm volatile("cp.async.wait_group 1;" ::: "memory")
#define CPW0() asm volatile("cp.async.wait_group 0;" ::: "memory")

// ---------------------------------------------------------------------------
// Kernel 1: x -> bf16 (zero-padded), sq from the SAME bf16 values.
// Block 0 additionally: label-dtype detection + counter reset.
// ---------------------------------------------------------------------------
__global__ void prep_kernel(const float* __restrict__ x,
                            const int* __restrict__ lab32) {
    int row  = blockIdx.x * (TPB / 32) + (threadIdx.x >> 5);
    int lane = threadIdx.x & 31;
    int k0   = lane * 8;
    const float* xr = x + (size_t)row * D;
    float s = 0.f;
    uint32_t w[4];
#pragma unroll
    for (int p = 0; p < 4; p++) {
        int ka = k0 + 2 * p, kb = ka + 1;
        float f0 = (ka < D) ? xr[ka] : 0.f;
        float f1 = (kb < D) ? xr[kb] : 0.f;
        __nv_bfloat16 b0 = __float2bfloat16(f0);
        __nv_bfloat16 b1 = __float2bfloat16(f1);
        float g0 = __bfloat162float(b0), g1 = __bfloat162float(b1);
        s = fmaf(g0, g0, s);
        s = fmaf(g1, g1, s);
        w[p] = (uint32_t)__bfloat16_as_ushort(b0) |
               ((uint32_t)__bfloat16_as_ushort(b1) << 16);
    }
    *(uint4*)(g_xb + (size_t)row * ROW_BYTES + k0 * 2) = make_uint4(w[0], w[1], w[2], w[3]);
#pragma unroll
    for (int o = 16; o; o >>= 1) s += __shfl_xor_sync(0xffffffffu, s, o);
    if (lane == 0) g_sq[row] = s;

    if (blockIdx.x == 0) {  // label dtype detection + counter reset
        __shared__ int any;
        if (threadIdx.x == 0) { any = 0; g_cnt = 0; }
        __syncthreads();
        int a = 0;
        for (int i = 2 * threadIdx.x + 1; i < NPTS; i += 2 * TPB) a |= lab32[i];
        if (a) atomicOr(&any, 1);
        __syncthreads();
        if (threadIdx.x == 0) g_is64 = (any == 0) ? 1 : 0;
    }
}

// ---------------------------------------------------------------------------
// Chunk prefetch via cp.async (one commit group = A+B of one chunk).
// ---------------------------------------------------------------------------
__device__ __forceinline__ void prefetch(uint32_t dynA, int buf,
                                         const unsigned char* gA,
                                         const unsigned char* gB, int ch, int t) {
    uint32_t bofs = buf ? TILE_BYTES : 0u;
#pragma unroll
    for (int p = 0; p < 4; p++) {
        int G = t + TPB * p;            // 0..1023
        int row = G >> 3, g = G & 7;
        uint32_t soff = bofs + row * 128 + ((g ^ (row & 7)) << 4);
        size_t   goff = (size_t)row * ROW_BYTES + (size_t)ch * 128 + (size_t)g * 16;
        CP16(dynA + soff, gA + goff);
        CP16(dynA + 2 * TILE_BYTES + soff, gB + goff);
    }
    CPC();
}

// ---------------------------------------------------------------------------
// Kernel 2: triangular grid of 128x128 Gram tiles, mma.sync bf16 m16n8k16,
// cp.async double buffer, 13 k-steps (K=208 covers D=200).
// ---------------------------------------------------------------------------
__global__ void __launch_bounds__(TPB, 2)
pair_kernel(const int* __restrict__ lab32, float* __restrict__ out) {
    extern __shared__ __align__(128) unsigned char dyn[];
    __shared__ float sqA[TM], sqB[TM];
    __shared__ int   lA[TM], lB[TM];
    __shared__ float red[TPB / 32];
    __shared__ int    s_last;
    __shared__ double dred[TPB];

    const int t    = threadIdx.x;
    const int wid  = t >> 5;
    const int lane = t & 31;

    // linearized upper-triangle map: blockIdx.x -> (ti, tj), ti <= tj
    int bl = blockIdx.x, ti = 0;
    while (bl >= NT - ti) { bl -= NT - ti; ti++; }
    const int tj = ti + bl;

    const uint32_t dynA = (uint32_t)__cvta_generic_to_shared(dyn);
    const unsigned char* gA = g_xb + (size_t)(ti * TM) * ROW_BYTES;
    const unsigned char* gB = g_xb + (size_t)(tj * TM) * ROW_BYTES;

    prefetch(dynA, 0, gA, gB, 0, t);
    prefetch(dynA, 1, gA, gB, 1, t);

    {
        int is64 = g_is64;
        if (t < TM) {
            int g = ti * TM + t;
            sqA[t] = g_sq[g];
            lA[t]  = is64 ? lab32[2 * g] : lab32[g];
        } else {
            int u = t - TM, g = tj * TM + u;
            sqB[u] = g_sq[g];
            lB[u]  = is64 ? lab32[2 * g] : lab32[g];
        }
    }

    const int warp_m = wid >> 1;   // 0..3 -> 32 rows
    const int warp_n = wid & 1;    // 0..1 -> 64 cols

    uint32_t abase[2], arx[2];
#pragma unroll
    for (int f = 0; f < 2; f++) {
        uint32_t arow = warp_m * 32 + f * 16 + (lane & 15);
        abase[f] = dynA + arow * 128;
        arx[f]   = arow & 7;
    }
    const uint32_t akg = lane >> 4;
    uint32_t bbase[4], brx[4];
#pragma unroll
    for (int h = 0; h < 4; h++) {
        uint32_t brow = warp_n * 64 + h * 16 + (lane & 7) + ((lane >> 4) << 3);
        bbase[h] = dynA + 2 * TILE_BYTES + brow * 128;
        brx[h]   = brow & 7;
    }
    const uint32_t bkg = (lane >> 3) & 1;

    float acc[2][8][4];
#pragma unroll
    for (int f = 0; f < 2; f++)
#pragma unroll
        for (int j = 0; j < 8; j++)
#pragma unroll
            for (int e = 0; e < 4; e++) acc[f][j][e] = 0.f;

// j-outer / f-inner: each B fragment consumed immediately (short live range)
#define KSTEP(ksv) do {                                                          \
    uint32_t a_[2][4];                                                           \
    _Pragma("unroll")                                                            \
    for (int f = 0; f < 2; f++) {                                                \
        uint32_t kg = (uint32_t)(ksv) * 2 + akg;                                 \
        uint32_t ad = abase[f] + bofs + ((kg ^ arx[f]) << 4);                    \
        asm volatile("ldmatrix.sync.aligned.m8n8.x4.shared.b16 {%0,%1,%2,%3}, [%4];" \
            : "=r"(a_[f][0]), "=r"(a_[f][1]), "=r"(a_[f][2]), "=r"(a_[f][3]) : "r"(ad)); \
    }                                                                            \
    _Pragma("unroll")                                                            \
    for (int h = 0; h < 4; h++) {                                                \
        uint32_t b0_, b1_, b2_, b3_;                                             \
        uint32_t kg = (uint32_t)(ksv) * 2 + bkg;                                 \
        uint32_t bd = bbase[h] + bofs + ((kg ^ brx[h]) << 4);                    \
        asm volatile("ldmatrix.sync.aligned.m8n8.x4.shared.b16 {%0,%1,%2,%3}, [%4];" \
            : "=r"(b0_), "=r"(b1_), "=r"(b2_), "=r"(b3_) : "r"(bd));             \
        _Pragma("unroll")                                                        \
        for (int f = 0; f < 2; f++) {                                            \
            asm volatile(                                                        \
                "mma.sync.aligned.m16n8k16.row.col.f32.bf16.bf16.f32 "           \
                "{%0,%1,%2,%3}, {%4,%5,%6,%7}, {%8,%9}, {%0,%1,%2,%3};"          \
                : "+f"(acc[f][2 * h][0]), "+f"(acc[f][2 * h][1]),                \
                  "+f"(acc[f][2 * h][2]), "+f"(acc[f][2 * h][3])                 \
                : "r"(a_[f][0]), "r"(a_[f][1]), "r"(a_[f][2]), "r"(a_[f][3]),    \
                  "r"(b0_), "r"(b1_));                                           \
            asm volatile(                                                        \
                "mma.sync.aligned.m16n8k16.row.col.f32.bf16.bf16.f32 "           \
                "{%0,%1,%2,%3}, {%4,%5,%6,%7}, {%8,%9}, {%0,%1,%2,%3};"          \
                : "+f"(acc[f][2 * h + 1][0]), "+f"(acc[f][2 * h + 1][1]),        \
                  "+f"(acc[f][2 * h + 1][2]), "+f"(acc[f][2 * h + 1][3])         \
                : "r"(a_[f][0]), "r"(a_[f][1]), "r"(a_[f][2]), "r"(a_[f][3]),    \
                  "r"(b2_), "r"(b3_));                                           \
        }                                                                        \
    }                                                                            \
} while (0)

#pragma unroll
    for (int ch = 0; ch < 4; ch++) {
        if (ch < 3) CPW1(); else CPW0();
        __syncthreads();
        const uint32_t bofs = (ch & 1) ? TILE_BYTES : 0u;
        KSTEP(0);
        if (ch < 3) { KSTEP(1); KSTEP(2); KSTEP(3); }  // 13 k-steps total
        __syncthreads();
        if (ch < 2) prefetch(dynA, ch & 1, gA, gB, ch + 2, t);
    }
#undef KSTEP

    // Epilogue: d2 -> dist -> signed, strict upper (n > m) predicate.
    float lsum = 0.f;
    const int qrow = lane >> 2;
    const int qcol = (lane & 3) * 2;
#pragma unroll
    for (int f = 0; f < 2; f++) {
        int m0 = warp_m * 32 + f * 16 + qrow;
#pragma unroll
        for (int j = 0; j < 8; j++) {
            int n0 = warp_n * 64 + j * 8 + qcol;
#pragma unroll
            for (int e = 0; e < 4; e++) {
                int m_loc = m0 + ((e >> 1) << 3);
                int n_loc = n0 + (e & 1);
                int gm = ti * TM + m_loc;
                int gn = tj * TM + n_loc;
                float d2   = sqA[m_loc] + sqB[n_loc] - 2.f * acc[f][j][e];
                float dist = sqrtf(fmaxf(d2, 0.f));
                float sgn  = (lA[m_loc] == lB[n_loc]) ? dist : -dist;
                if (gn > gm) lsum += sgn;
            }
        }
    }
#pragma unroll
    for (int o = 16; o; o >>= 1) lsum += __shfl_xor_sync(0xffffffffu, lsum, o);
    if (lane == 0) red[wid] = lsum;
    __syncthreads();
    if (t == 0) {
        float s = 0.f;
#pragma unroll
        for (int w = 0; w < TPB / 32; w++) s += red[w];
        g_part[blockIdx.x] = s;
    }

    // ---- last-CTA-done fused final reduction (deterministic order) ----
    __threadfence();
    if (t == 0) {
        unsigned old = atomicAdd(&g_cnt, 1u);
        s_last = (old == NTRI - 1) ? 1 : 0;
    }
    __syncthreads();
    if (s_last) {
        __threadfence();
        double a = 0.0;
        for (int i = t; i < NTRI; i += TPB) a += (double)g_part[i];
        dred[t] = a;
        __syncthreads();
        for (int o = TPB / 2; o; o >>= 1) {
            if (t < o) dred[t] += dred[t + o];
            __syncthreads();
        }
        if (t == 0) out[0] = (float)(2.0 * dred[0] / (double)NPTS);
    }
}

// ---------------------------------------------------------------------------
extern "C" void kernel_launch(void* const* d_in, const int* in_sizes, int n_in,
                              void* d_out, int out_size) {
    const float* x     = (const float*)d_in[0];
    const int*   lab32 = (const int*)d_in[1];
    float*       outp  = (float*)d_out;

    cudaFuncSetAttribute(pair_kernel, cudaFuncAttributeMaxDynamicSharedMemorySize,
                         SMEM_DYN);

    prep_kernel<<<NPTS / (TPB / 32), TPB>>>(x, lab32);
    pair_kernel<<<NTRI, TPB, SMEM_DYN>>>(lab32, outp);
}